// round 14
// baseline (speedup 1.0000x reference)
#include <cuda_runtime.h>
#include <cstddef>
#include <cstdint>

typedef unsigned long long ull;

// ---------------- gmem scratch ----------------
__device__ float g_h1 [100 * 21 * 4096];
__device__ float g_y  [100 *  9 * 4096];
__device__ float g_h11[200 *  5 * 4096];
// transposed weights (filled by k0 each launch)
__device__ float g_w2T [1000 * 200];    // w2_1: [cik][co]
__device__ float g_wdT [100 * 200];     // wd_1: [ci][co]
__device__ float g_hw1T[8 * 200 * 100]; // hw1:  [task][c2][c1]
__device__ float g_w20T[500 * 100];     // w2_0: [cik][co]
__device__ float g_w11T[500 * 200];     // w1_1: [cik][co]
__device__ float g_wd0T[30 * 100];      // wd_0: [ci][co]
__device__ float g_w10T[150 * 100];     // w1_0: [cik][co]

// ---------------- helpers ----------------
__device__ __forceinline__ void cp16(float* dst_smem, const float* src) {
    uint32_t s = (uint32_t)__cvta_generic_to_shared(dst_smem);
    asm volatile("cp.async.cg.shared.global [%0], [%1], 16;\n" :: "r"(s), "l"(src));
}
__device__ __forceinline__ void cp_commit() { asm volatile("cp.async.commit_group;\n"); }
__device__ __forceinline__ void cp_wait0()  { asm volatile("cp.async.wait_group 0;\n"); }

__device__ __forceinline__ ull pack2(float x, float y) {
    ull r; asm("mov.b64 %0, {%1, %2};" : "=l"(r) : "f"(x), "f"(y)); return r;
}
__device__ __forceinline__ ull bcast2(float x) { return pack2(x, x); }
__device__ __forceinline__ float2 unpack2(ull v) {
    float2 f; asm("mov.b64 {%0, %1}, %2;" : "=f"(f.x), "=f"(f.y) : "l"(v)); return f;
}
__device__ __forceinline__ void fma2(ull& d, ull a, ull b) {
    asm("fma.rn.f32x2 %0, %1, %2, %3;" : "=l"(d) : "l"(a), "l"(b), "l"(d));
}

// =====================================================================================
// K0: weight transposes
// =====================================================================================
__global__ __launch_bounds__(512, 2) void k0(
    const float* __restrict__ w2_1, const float* __restrict__ wd_1,
    const float* __restrict__ hw1,  const float* __restrict__ w2_0,
    const float* __restrict__ w1_1, const float* __restrict__ wd_0,
    const float* __restrict__ w1_0)
{
    const int i = blockIdx.x * blockDim.x + threadIdx.x;
    const int n = blockDim.x * gridDim.x;
    for (int j = i; j < 200000; j += n) {
        int cik = j / 200, co = j - cik * 200;
        g_w2T[j] = __ldg(w2_1 + co * 1000 + cik);
    }
    for (int j = i; j < 20000; j += n) {
        int ci = j / 200, co = j - ci * 200;
        g_wdT[j] = __ldg(wd_1 + co * 100 + ci);
    }
    for (int j = i; j < 160000; j += n) {
        int t = j / 20000; int r = j - t * 20000; int c2 = r / 100; int c1 = r - c2 * 100;
        g_hw1T[j] = __ldg(hw1 + ((size_t)t * 100 + c1) * 200 + c2);
    }
    for (int j = i; j < 50000; j += n) {
        int cik = j / 100, co = j - cik * 100;
        g_w20T[j] = __ldg(w2_0 + co * 500 + cik);
    }
    for (int j = i; j < 100000; j += n) {
        int cik = j / 200, co = j - cik * 200;
        g_w11T[j] = __ldg(w1_1 + co * 500 + cik);
    }
    for (int j = i; j < 3000; j += n) {
        int ci = j / 100, co = j - ci * 100;
        g_wd0T[j] = __ldg(wd_0 + co * 30 + ci);
    }
    for (int j = i; j < 15000; j += n) {
        int cik = j / 100, co = j - cik * 100;
        g_w10T[j] = __ldg(w1_0 + co * 150 + cik);
    }
}

// =====================================================================================
// K1: h1[co][t][b] = relu(conv1_0(x))  f32x2, 3 t-phases  [R11 form]
// =====================================================================================
#define K1_X 12000
__global__ __launch_bounds__(512, 2) void k1(
    const float* __restrict__ x, const float* __restrict__ b1_0)
{
    extern __shared__ float sm[];
    const int tid = threadIdx.x;
    const int b0  = blockIdx.x * 16;

    for (int i = tid; i < K1_X; i += 512) {
        int ci = i / 400; int r = i - ci * 400; int bl = r / 25; int tau = r - bl * 25;
        sm[(ci * 25 + tau) * 16 + bl] = x[(size_t)(b0 + bl) * 7680 + ci * 256 + 231 + tau];
    }
    __syncthreads();

    const int cop = tid >> 3;
    const int bgp = tid & 7;
    if (cop < 50) {
        const int co0 = 2 * cop, co1 = co0 + 1;
        const float bi0 = __ldg(b1_0 + co0), bi1 = __ldg(b1_0 + co1);
        #pragma unroll 1
        for (int ph = 0; ph < 3; ph++) {
            const int t0 = ph * 7;
            ull a0[7], a1[7];
            {
                ull p0 = bcast2(bi0), p1 = bcast2(bi1);
                #pragma unroll
                for (int tt = 0; tt < 7; tt++) { a0[tt] = p0; a1[tt] = p1; }
            }
            for (int ci = 0; ci < 30; ci++) {
                const float* xp = &sm[(ci * 25 + t0) * 16 + bgp * 2];
                ull v[11];
                #pragma unroll
                for (int u = 0; u < 11; u++) v[u] = *(const ull*)&xp[u * 16];
                #pragma unroll
                for (int k = 0; k < 5; k++) {
                    float2 w = *(const float2*)&g_w10T[(ci * 5 + k) * 100 + co0];
                    ull wx = bcast2(w.x), wy = bcast2(w.y);
                    #pragma unroll
                    for (int tt = 0; tt < 7; tt++) {
                        fma2(a0[tt], wx, v[tt + k]);
                        fma2(a1[tt], wy, v[tt + k]);
                    }
                }
            }
            #pragma unroll
            for (int tt = 0; tt < 7; tt++) {
                float2 f0 = unpack2(a0[tt]);
                float2 f1 = unpack2(a1[tt]);
                f0.x = fmaxf(f0.x, 0.f); f0.y = fmaxf(f0.y, 0.f);
                f1.x = fmaxf(f1.x, 0.f); f1.y = fmaxf(f1.y, 0.f);
                *(float2*)&g_h1[((size_t)co0 * 21 + t0 + tt) * 4096 + b0 + bgp * 2] = f0;
                *(float2*)&g_h1[((size_t)co1 * 21 + t0 + tt) * 4096 + b0 + bgp * 2] = f1;
            }
        }
    }
}

// =====================================================================================
// K2: y = relu(relu(conv2_0(h1)) + bd0 + wd0*x) at 9 pts.  f32x2, j-split.  [R13 form]
// =====================================================================================
#define K2_HMAX (100 * 13 * 16)
#define K2_XMAX (30 * 5 * 16)

template<int JC, int TC, int JL>
__device__ __forceinline__ void k2_body(
    const float* __restrict__ h1s, const float* __restrict__ xs2,
    const float* __restrict__ b2_0, const float* __restrict__ bd_0,
    int co0, int bgp, int b0)
{
    const int co1 = co0 + 1;
    ull a[2][JC];
    {
        ull b0v = bcast2(__ldg(b2_0 + co0));
        ull b1v = bcast2(__ldg(b2_0 + co1));
        #pragma unroll
        for (int j = 0; j < JC; j++) { a[0][j] = b0v; a[1][j] = b1v; }
    }
    for (int ci = 0; ci < 100; ci++) {
        const float* hp = &h1s[(ci * TC) * 16 + bgp * 2];
        ull v[TC];
        #pragma unroll
        for (int t = 0; t < TC; t++) v[t] = *(const ull*)&hp[t * 16];
        #pragma unroll
        for (int k = 0; k < 5; k++) {
            float2 w = *(const float2*)&g_w20T[(ci * 5 + k) * 100 + co0];
            ull wx = bcast2(w.x), wy = bcast2(w.y);
            #pragma unroll
            for (int j = 0; j < JC; j++) {
                fma2(a[0][j], wx, v[2 * j + k]);
                fma2(a[1][j], wy, v[2 * j + k]);
            }
        }
    }
    {
        float bd0v = __ldg(bd_0 + co0), bd1v = __ldg(bd_0 + co1);
        #pragma unroll
        for (int j = 0; j < JC; j++) {
            float2 f0 = unpack2(a[0][j]);
            float2 f1 = unpack2(a[1][j]);
            a[0][j] = pack2(fmaxf(f0.x, 0.f) + bd0v, fmaxf(f0.y, 0.f) + bd0v);
            a[1][j] = pack2(fmaxf(f1.x, 0.f) + bd1v, fmaxf(f1.y, 0.f) + bd1v);
        }
    }
    for (int ci = 0; ci < 30; ci++) {
        float2 w = *(const float2*)&g_wd0T[ci * 100 + co0];
        ull wx = bcast2(w.x), wy = bcast2(w.y);
        const float* xp = &xs2[(ci * JC) * 16 + bgp * 2];
        #pragma unroll
        for (int j = 0; j < JC; j++) {
            ull xv = *(const ull*)&xp[j * 16];
            fma2(a[0][j], wx, xv);
            fma2(a[1][j], wy, xv);
        }
    }
    #pragma unroll
    for (int j = 0; j < JC; j++) {
        float2 f0 = unpack2(a[0][j]);
        float2 f1 = unpack2(a[1][j]);
        f0.x = fmaxf(f0.x, 0.f); f0.y = fmaxf(f0.y, 0.f);
        f1.x = fmaxf(f1.x, 0.f); f1.y = fmaxf(f1.y, 0.f);
        *(float2*)&g_y[((size_t)co0 * 9 + JL + j) * 4096 + b0 + bgp * 2] = f0;
        *(float2*)&g_y[((size_t)co1 * 9 + JL + j) * 4096 + b0 + bgp * 2] = f1;
    }
}

__global__ __launch_bounds__(512, 2) void k2(
    const float* __restrict__ x,
    const float* __restrict__ b2_0, const float* __restrict__ bd_0)
{
    extern __shared__ float sm[];
    float* h1s = sm;
    float* xs2 = sm + K2_HMAX;
    const int tid = threadIdx.x;
    const int bq  = blockIdx.x >> 1;
    const int jr  = blockIdx.x & 1;
    const int b0  = bq * 16;
    const int jlo  = jr ? 4 : 0;
    const int jcnt = jr ? 5 : 4;
    const int tlo  = jr ? 8 : 0;
    const int tcnt = jr ? 13 : 12;

    const int nh = (100 * tcnt * 16) >> 2;
    for (int i = tid; i < nh; i += 512) {
        int row = i >> 2, q = i & 3;
        int ci = row / tcnt, tt = row - ci * tcnt;
        cp16(&h1s[row * 16 + 4 * q],
             &g_h1[((size_t)ci * 21 + tlo + tt) * 4096 + b0 + 4 * q]);
    }
    cp_commit();

    const int nx = 30 * jcnt * 16;
    for (int i = tid; i < nx; i += 512) {
        int bl = i & 15; int r = i >> 4; int jj = r % jcnt; int ci = r / jcnt;
        xs2[(ci * jcnt + jj) * 16 + bl] =
            x[(size_t)(b0 + bl) * 7680 + ci * 256 + 239 + 2 * (jlo + jj)];
    }

    cp_wait0();
    __syncthreads();

    const int cop = tid >> 3;
    const int bgp = tid & 7;
    if (cop < 50) {
        const int co0 = 2 * cop;
        if (jr == 0) k2_body<4, 12, 0>(h1s, xs2, b2_0, bd_0, co0, bgp, b0);
        else         k2_body<5, 13, 4>(h1s, xs2, b2_0, bd_0, co0, bgp, b0);
    }
}

// =====================================================================================
// K3: h11 = relu(conv1_1(y, dil=2)) at 5 pts.  BATCH-PACKED f32x2, two i-passes.
// Thread = (co-pair cog<100, batch-quad bg); acc ull over batch-pairs; v as ulonglong2.
// Pass A: i=0..2 (24 acc regs + 28 window); pass B: i=3..4 (16 + 24).
// =====================================================================================
#define K3_Y  14400                 // y tile [ci][j][16b]
__global__ __launch_bounds__(512, 2) void k3(const float* __restrict__ b1_1)
{
    extern __shared__ float sm[];
    float* ys = sm;
    const int tid = threadIdx.x;
    const int b0  = blockIdx.x * 16;

    for (int i = tid; i < 3600; i += 512) {
        int cij = i >> 2, q = i & 3;
        cp16(&ys[cij * 16 + 4 * q], &g_y[(size_t)cij * 4096 + b0 + 4 * q]);
    }
    cp_commit();
    cp_wait0();
    __syncthreads();

    const int cog = tid >> 2;          // 0..127, active < 100 (co pairs)
    const int bg  = tid & 3;           // batch quad: 4 batches = 2 ull pairs
    if (cog < 100) {
        const int co0 = 2 * cog, co1 = co0 + 1;
        const float bi0 = __ldg(b1_1 + co0), bi1 = __ldg(b1_1 + co1);

        // ---------------- pass A: i = 0,1,2  (window j = 0..6) ----------------
        {
            ull a0[3][2], a1[3][2];
            {
                ull p0 = bcast2(bi0), p1 = bcast2(bi1);
                #pragma unroll
                for (int i = 0; i < 3; i++) {
                    a0[i][0] = p0; a0[i][1] = p0;
                    a1[i][0] = p1; a1[i][1] = p1;
                }
            }
            for (int ci = 0; ci < 100; ci++) {
                const float* yp = &ys[(ci * 9) * 16 + bg * 4];
                ulonglong2 v[7];
                #pragma unroll
                for (int j = 0; j < 7; j++) v[j] = *(const ulonglong2*)&yp[j * 16];
                #pragma unroll
                for (int k = 0; k < 5; k++) {
                    float2 w = *(const float2*)&g_w11T[(ci * 5 + k) * 200 + co0];
                    ull wx = bcast2(w.x), wy = bcast2(w.y);
                    #pragma unroll
                    for (int i = 0; i < 3; i++) {
                        fma2(a0[i][0], wx, v[k + i].x);
                        fma2(a0[i][1], wx, v[k + i].y);
                        fma2(a1[i][0], wy, v[k + i].x);
                        fma2(a1[i][1], wy, v[k + i].y);
                    }
                }
            }
            #pragma unroll
            for (int i = 0; i < 3; i++) {
                float2 l0 = unpack2(a0[i][0]), h0 = unpack2(a0[i][1]);
                float2 l1 = unpack2(a1[i][0]), h1 = unpack2(a1[i][1]);
                float4 r0 = make_float4(fmaxf(l0.x, 0.f), fmaxf(l0.y, 0.f),
                                        fmaxf(h0.x, 0.f), fmaxf(h0.y, 0.f));
                float4 r1 = make_float4(fmaxf(l1.x, 0.f), fmaxf(l1.y, 0.f),
                                        fmaxf(h1.x, 0.f), fmaxf(h1.y, 0.f));
                *(float4*)&g_h11[((size_t)co0 * 5 + i) * 4096 + b0 + bg * 4] = r0;
                *(float4*)&g_h11[((size_t)co1 * 5 + i) * 4096 + b0 + bg * 4] = r1;
            }
        }

        // ---------------- pass B: i = 3,4  (window j = 3..8) ----------------
        {
            ull a0[2][2], a1[2][2];
            {
                ull p0 = bcast2(bi0), p1 = bcast2(bi1);
                #pragma unroll
                for (int i = 0; i < 2; i++) {
                    a0[i][0] = p0; a0[i][1] = p0;
                    a1[i][0] = p1; a1[i][1] = p1;
                }
            }
            for (int ci = 0; ci < 100; ci++) {
                const float* yp = &ys[(ci * 9) * 16 + bg * 4];
                ulonglong2 v[6];
                #pragma unroll
                for (int j = 0; j < 6; j++) v[j] = *(const ulonglong2*)&yp[(j + 3) * 16];
                #pragma unroll
                for (int k = 0; k < 5; k++) {
                    float2 w = *(const float2*)&g_w11T[(ci * 5 + k) * 200 + co0];
                    ull wx = bcast2(w.x), wy = bcast2(w.y);
                    #pragma unroll
                    for (int i = 0; i < 2; i++) {     // window idx = k+i (j = k+i+3)
                        fma2(a0[i][0], wx, v[k + i].x);
                        fma2(a0[i][1], wx, v[k + i].y);
                        fma2(a1[i][0], wy, v[k + i].x);
                        fma2(a1[i][1], wy, v[k + i].y);
                    }
                }
            }
            #pragma unroll
            for (int i = 0; i < 2; i++) {
                float2 l0 = unpack2(a0[i][0]), h0 = unpack2(a0[i][1]);
                float2 l1 = unpack2(a1[i][0]), h1 = unpack2(a1[i][1]);
                float4 r0 = make_float4(fmaxf(l0.x, 0.f), fmaxf(l0.y, 0.f),
                                        fmaxf(h0.x, 0.f), fmaxf(h0.y, 0.f));
                float4 r1 = make_float4(fmaxf(l1.x, 0.f), fmaxf(l1.y, 0.f),
                                        fmaxf(h1.x, 0.f), fmaxf(h1.y, 0.f));
                *(float4*)&g_h11[((size_t)co0 * 5 + i + 3) * 4096 + b0 + bg * 4] = r0;
                *(float4*)&g_h11[((size_t)co1 * 5 + i + 3) * 4096 + b0 + bg * 4] = r1;
            }
        }
    }
}

// =====================================================================================
// K4: feat = relu(relu(conv2_1(h11)@t=255) + bd1 + wd1*y[t=255]); fused head. [R10 form]
// =====================================================================================
#define K4_H    16000
#define K4_YR   1600
#define K4_FT   3216
#define K4_HH   1664
__global__ __launch_bounds__(512, 2) void k4(
    const int* __restrict__ task_labels,
    const float* __restrict__ b2_1, const float* __restrict__ bd_1,
    const float* __restrict__ hb1,
    const float* __restrict__ hw2, const float* __restrict__ hb2,
    float* __restrict__ out)
{
    extern __shared__ float sm[];
    float* h11s = sm;
    float* yres = sm + K4_H;
    float* feat = sm + K4_H + K4_YR;
    float* smH  = sm + K4_H + K4_YR + K4_FT;
    const int tid = threadIdx.x;
    const int b0  = blockIdx.x * 16;

    const int cog = tid >> 2;
    const int bg  = tid & 3;
    const bool act = (cog < 100);
    const int co0 = 2 * cog, co1 = 2 * cog + 1;

    for (int i = tid; i < 4000; i += 512) {
        int cik = i >> 2, q = i & 3;
        cp16(&h11s[cik * 16 + 4 * q], &g_h11[(size_t)cik * 4096 + b0 + 4 * q]);
    }
    cp_commit();

    for (int i = tid; i < K4_YR; i += 512) {
        int blx = i & 15, ci = i >> 4;
        yres[ci * 16 + blx] = g_y[((size_t)ci * 9 + 8) * 4096 + b0 + blx];
    }

    cp_wait0();
    __syncthreads();

    if (act) {
        ull c0l = 0, c0h = 0, c1l = 0, c1h = 0;
        #pragma unroll 2
        for (int q = 0; q < 250; q++) {
            ulonglong2 av0 = *(const ulonglong2*)&h11s[(4 * q + 0) * 16 + bg * 4];
            ulonglong2 av1 = *(const ulonglong2*)&h11s[(4 * q + 1) * 16 + bg * 4];
            ulonglong2 av2 = *(const ulonglong2*)&h11s[(4 * q + 2) * 16 + bg * 4];
            ulonglong2 av3 = *(const ulonglong2*)&h11s[(4 * q + 3) * 16 + bg * 4];
            float2 w0 = *(const float2*)&g_w2T[(4 * q + 0) * 200 + co0];
            float2 w1 = *(const float2*)&g_w2T[(4 * q + 1) * 200 + co0];
            float2 w2 = *(const float2*)&g_w2T[(4 * q + 2) * 200 + co0];
            float2 w3 = *(const float2*)&g_w2T[(4 * q + 3) * 200 + co0];
            ull w0x = bcast2(w0.x), w0y = bcast2(w0.y);
            ull w1x = bcast2(w1.x), w1y = bcast2(w1.y);
            ull w2x = bcast2(w2.x), w2y = bcast2(w2.y);
            ull w3x = bcast2(w3.x), w3y = bcast2(w3.y);
            fma2(c0l, w0x, av0.x); fma2(c0h, w0x, av0.y);
            fma2(c1l, w0y, av0.x); fma2(c1h, w0y, av0.y);
            fma2(c0l, w1x, av1.x); fma2(c0h, w1x, av1.y);
            fma2(c1l, w1y, av1.x); fma2(c1h, w1y, av1.y);
            fma2(c0l, w2x, av2.x); fma2(c0h, w2x, av2.y);
            fma2(c1l, w2y, av2.x); fma2(c1h, w2y, av2.y);
            fma2(c0l, w3x, av3.x); fma2(c0h, w3x, av3.y);
            fma2(c1l, w3y, av3.x); fma2(c1h, w3y, av3.y);
        }

        ull r0l = 0, r0h = 0, r1l = 0, r1h = 0;
        #pragma unroll 5
        for (int q = 0; q < 25; q++) {
            ulonglong2 yv0 = *(const ulonglong2*)&yres[(4 * q + 0) * 16 + bg * 4];
            ulonglong2 yv1 = *(const ulonglong2*)&yres[(4 * q + 1) * 16 + bg * 4];
            ulonglong2 yv2 = *(const ulonglong2*)&yres[(4 * q + 2) * 16 + bg * 4];
            ulonglong2 yv3 = *(const ulonglong2*)&yres[(4 * q + 3) * 16 + bg * 4];
            float2 w0 = *(const float2*)&g_wdT[(4 * q + 0) * 200 + co0];
            float2 w1 = *(const float2*)&g_wdT[(4 * q + 1) * 200 + co0];
            float2 w2 = *(const float2*)&g_wdT[(4 * q + 2) * 200 + co0];
            float2 w3 = *(const float2*)&g_wdT[(4 * q + 3) * 200 + co0];
            ull w0x = bcast2(w0.x), w0y = bcast2(w0.y);
            ull w1x = bcast2(w1.x), w1y = bcast2(w1.y);
            ull w2x = bcast2(w2.x), w2y = bcast2(w2.y);
            ull w3x = bcast2(w3.x), w3y = bcast2(w3.y);
            fma2(r0l, w0x, yv0.x); fma2(r0h, w0x, yv0.y);
            fma2(r1l, w0y, yv0.x); fma2(r1h, w0y, yv0.y);
            fma2(r0l, w1x, yv1.x); fma2(r0h, w1x, yv1.y);
            fma2(r1l, w1y, yv1.x); fma2(r1h, w1y, yv1.y);
            fma2(r0l, w2x, yv2.x); fma2(r0h, w2x, yv2.y);
            fma2(r1l, w2y, yv2.x); fma2(r1h, w2y, yv2.y);
            fma2(r0l, w3x, yv3.x); fma2(r0h, w3x, yv3.y);
            fma2(r1l, w3y, yv3.x); fma2(r1h, w3y, yv3.y);
        }

        float b2v0 = __ldg(b2_1 + co0), bdv0 = __ldg(bd_1 + co0);
        float b2v1 = __ldg(b2_1 + co1), bdv1 = __ldg(bd_1 + co1);
        float2 cl0 = unpack2(c0l), ch0 = unpack2(c0h);
        float2 cl1 = unpack2(c1l), ch1 = unpack2(c1h);
        float2 sl0 = unpack2(r0l), sh0 = unpack2(r0h);
        float2 sl1 = unpack2(r1l), sh1 = unpack2(r1h);
        float conv0[4] = { cl0.x, cl0.y, ch0.x, ch0.y };
        float conv1[4] = { cl1.x, cl1.y, ch1.x, ch1.y };
        float res0[4]  = { sl0.x, sl0.y, sh0.x, sh0.y };
        float res1[4]  = { sl1.x, sl1.y, sh1.x, sh1.y };
        #pragma unroll
        for (int b = 0; b < 4; b++) {
            int blx = bg * 4 + b;
            feat[blx * 201 + co0] = fmaxf(fmaxf(conv0[b] + b2v0, 0.f) + bdv0 + res0[b], 0.f);
            feat[blx * 201 + co1] = fmaxf(fmaxf(conv1[b] + b2v1, 0.f) + bdv1 + res1[b], 0.f);
        }
    }
    __syncthreads();

    for (int o = tid; o < 800; o += 512) {
        int blx = o / 50, c1p = o - blx * 50;
        int task = __ldg(task_labels + b0 + blx);
        const float* Wt = g_hw1T + task * 20000 + c1p * 2;
        const float* fr = &feat[blx * 201];
        ull acc = 0;
        #pragma unroll 4
        for (int c2 = 0; c2 < 200; c2++) {
            float2 w = *(const float2*)&Wt[c2 * 100];
            ull wp; asm("mov.b64 %0, {%1, %2};" : "=l"(wp) : "f"(w.x), "f"(w.y));
            fma2(acc, bcast2(fr[c2]), wp);
        }
        float2 s = unpack2(acc);
        float2 hb = *(const float2*)&hb1[task * 100 + c1p * 2];
        smH[blx * 104 + c1p * 2 + 0] = tanhf(s.x + hb.x);
        smH[blx * 104 + c1p * 2 + 1] = tanhf(s.y + hb.y);
    }
    __syncthreads();

    if (tid < 16) {
        int blx = tid;
        int task = __ldg(task_labels + b0 + blx);
        const float4* W = (const float4*)(hw2 + task * 100);
        const float* hr = &smH[blx * 104];
        float a0 = 0.f, a1 = 0.f, a2 = 0.f, a3 = 0.f;
        #pragma unroll 5
        for (int q = 0; q < 25; q++) {
            float4 wv = __ldg(W + q);
            a0 = fmaf(hr[4 * q + 0], wv.x, a0);
            a1 = fmaf(hr[4 * q + 1], wv.y, a1);
            a2 = fmaf(hr[4 * q + 2], wv.z, a2);
            a3 = fmaf(hr[4 * q + 3], wv.w, a3);
        }
        out[b0 + blx] = (a0 + a1) + (a2 + a3) + __ldg(hb2 + task);
    }
}

// =====================================================================================
extern "C" void kernel_launch(void* const* d_in, const int* in_sizes, int n_in,
                              void* d_out, int out_size)
{
    const float* x    = (const float*)d_in[0];
    const int*   tl   = (const int*)  d_in[1];
    const float* w1_0 = (const float*)d_in[2];
    const float* b1_0 = (const float*)d_in[3];
    const float* w2_0 = (const float*)d_in[4];
    const float* b2_0 = (const float*)d_in[5];
    const float* wd_0 = (const float*)d_in[6];
    const float* bd_0 = (const float*)d_in[7];
    const float* w1_1 = (const float*)d_in[8];
    const float* b1_1 = (const float*)d_in[9];
    const float* w2_1 = (const float*)d_in[10];
    const float* b2_1 = (const float*)d_in[11];
    const float* wd_1 = (const float*)d_in[12];
    const float* bd_1 = (const float*)d_in[13];
    const float* hw1  = (const float*)d_in[14];
    const float* hb1  = (const float*)d_in[15];
    const float* hw2  = (const float*)d_in[16];
    const float* hb2  = (const float*)d_in[17];
    float* out = (float*)d_out;

    const int s1 = K1_X * 4;
    const int s2 = (K2_HMAX + K2_XMAX) * 4;
    const int s3 = K3_Y * 4;
    const int s4 = (K4_H + K4_YR + K4_FT + K4_HH) * 4;
    cudaFuncSetAttribute(k1, cudaFuncAttributeMaxDynamicSharedMemorySize, s1);
    cudaFuncSetAttribute(k2, cudaFuncAttributeMaxDynamicSharedMemorySize, s2);
    cudaFuncSetAttribute(k3, cudaFuncAttributeMaxDynamicSharedMemorySize, s3);
    cudaFuncSetAttribute(k4, cudaFuncAttributeMaxDynamicSharedMemorySize, s4);

    k0<<<148, 512>>>(w2_1, wd_1, hw1, w2_0, w1_1, wd_0, w1_0);
    k1<<<256, 512, s1>>>(x, b1_0);
    k2<<<512, 512, s2>>>(x, b2_0, bd_0);
    k3<<<256, 512, s3>>>(b1_1);
    k4<<<256, 512, s4>>>(tl, b2_1, bd_1, hb1, hw2, hb2, out);
}

// round 15
// speedup vs baseline: 1.0268x; 1.0268x over previous
#include <cuda_runtime.h>
#include <cstddef>
#include <cstdint>

typedef unsigned long long ull;

// ---------------- gmem scratch ----------------
__device__ float g_h1 [100 * 21 * 4096];
__device__ float g_y  [100 *  9 * 4096];
__device__ float g_h11[200 *  5 * 4096];
// transposed weights (filled by k0 each launch)
__device__ float g_w2T [1000 * 200];    // w2_1: [cik][co]
__device__ float g_wdT [100 * 200];     // wd_1: [ci][co]
__device__ float g_hw1T[8 * 200 * 100]; // hw1:  [task][c2][c1]
__device__ float g_w20T[500 * 100];     // w2_0: [cik][co]
__device__ float g_w11T[500 * 200];     // w1_1: [cik][co]
__device__ float g_wd0T[30 * 100];      // wd_0: [ci][co]
__device__ float g_w10T[150 * 100];     // w1_0: [cik][co]

// ---------------- helpers ----------------
__device__ __forceinline__ void cp16(float* dst_smem, const float* src) {
    uint32_t s = (uint32_t)__cvta_generic_to_shared(dst_smem);
    asm volatile("cp.async.cg.shared.global [%0], [%1], 16;\n" :: "r"(s), "l"(src));
}
__device__ __forceinline__ void cp_commit() { asm volatile("cp.async.commit_group;\n"); }
__device__ __forceinline__ void cp_wait0()  { asm volatile("cp.async.wait_group 0;\n"); }

__device__ __forceinline__ ull pack2(float x, float y) {
    ull r; asm("mov.b64 %0, {%1, %2};" : "=l"(r) : "f"(x), "f"(y)); return r;
}
__device__ __forceinline__ ull bcast2(float x) { return pack2(x, x); }
__device__ __forceinline__ float2 unpack2(ull v) {
    float2 f; asm("mov.b64 {%0, %1}, %2;" : "=f"(f.x), "=f"(f.y) : "l"(v)); return f;
}
__device__ __forceinline__ void fma2(ull& d, ull a, ull b) {
    asm("fma.rn.f32x2 %0, %1, %2, %3;" : "=l"(d) : "l"(a), "l"(b), "l"(d));
}
__device__ __forceinline__ void fma4(float4& a, float w, const float4& v) {
    a.x = fmaf(w, v.x, a.x); a.y = fmaf(w, v.y, a.y);
    a.z = fmaf(w, v.z, a.z); a.w = fmaf(w, v.w, a.w);
}

// =====================================================================================
// K0: weight transposes
// =====================================================================================
__global__ __launch_bounds__(512, 2) void k0(
    const float* __restrict__ w2_1, const float* __restrict__ wd_1,
    const float* __restrict__ hw1,  const float* __restrict__ w2_0,
    const float* __restrict__ w1_1, const float* __restrict__ wd_0,
    const float* __restrict__ w1_0)
{
    const int i = blockIdx.x * blockDim.x + threadIdx.x;
    const int n = blockDim.x * gridDim.x;
    for (int j = i; j < 200000; j += n) {
        int cik = j / 200, co = j - cik * 200;
        g_w2T[j] = __ldg(w2_1 + co * 1000 + cik);
    }
    for (int j = i; j < 20000; j += n) {
        int ci = j / 200, co = j - ci * 200;
        g_wdT[j] = __ldg(wd_1 + co * 100 + ci);
    }
    for (int j = i; j < 160000; j += n) {
        int t = j / 20000; int r = j - t * 20000; int c2 = r / 100; int c1 = r - c2 * 100;
        g_hw1T[j] = __ldg(hw1 + ((size_t)t * 100 + c1) * 200 + c2);
    }
    for (int j = i; j < 50000; j += n) {
        int cik = j / 100, co = j - cik * 100;
        g_w20T[j] = __ldg(w2_0 + co * 500 + cik);
    }
    for (int j = i; j < 100000; j += n) {
        int cik = j / 200, co = j - cik * 200;
        g_w11T[j] = __ldg(w1_1 + co * 500 + cik);
    }
    for (int j = i; j < 3000; j += n) {
        int ci = j / 100, co = j - ci * 100;
        g_wd0T[j] = __ldg(wd_0 + co * 30 + ci);
    }
    for (int j = i; j < 15000; j += n) {
        int cik = j / 100, co = j - cik * 100;
        g_w10T[j] = __ldg(w1_0 + co * 150 + cik);
    }
}

// =====================================================================================
// K1: h1 = relu(conv1_0(x)).  f32x2, 3 t-phases.  8 batches/CTA, 256 thr, occ 4.
// =====================================================================================
#define K1_X 6000                   // [(ci*25+tau)*8 + bl]
__global__ __launch_bounds__(256, 4) void k1(
    const float* __restrict__ x, const float* __restrict__ b1_0)
{
    extern __shared__ float sm[];
    const int tid = threadIdx.x;
    const int b0  = blockIdx.x * 8;

    for (int i = tid; i < K1_X; i += 256) {
        int ci = i / 200; int r = i - ci * 200; int bl = r / 25; int tau = r - bl * 25;
        sm[(ci * 25 + tau) * 8 + bl] = x[(size_t)(b0 + bl) * 7680 + ci * 256 + 231 + tau];
    }
    __syncthreads();

    const int cop = tid >> 2;          // 0..63, active < 50
    const int bgp = tid & 3;           // batch pair (8 batches = 4 pairs)
    if (cop < 50) {
        const int co0 = 2 * cop, co1 = co0 + 1;
        const float bi0 = __ldg(b1_0 + co0), bi1 = __ldg(b1_0 + co1);
        #pragma unroll 1
        for (int ph = 0; ph < 3; ph++) {
            const int t0 = ph * 7;
            ull a0[7], a1[7];
            {
                ull p0 = bcast2(bi0), p1 = bcast2(bi1);
                #pragma unroll
                for (int tt = 0; tt < 7; tt++) { a0[tt] = p0; a1[tt] = p1; }
            }
            for (int ci = 0; ci < 30; ci++) {
                const float* xp = &sm[(ci * 25 + t0) * 8 + bgp * 2];
                ull v[11];
                #pragma unroll
                for (int u = 0; u < 11; u++) v[u] = *(const ull*)&xp[u * 8];
                #pragma unroll
                for (int k = 0; k < 5; k++) {
                    float2 w = *(const float2*)&g_w10T[(ci * 5 + k) * 100 + co0];
                    ull wx = bcast2(w.x), wy = bcast2(w.y);
                    #pragma unroll
                    for (int tt = 0; tt < 7; tt++) {
                        fma2(a0[tt], wx, v[tt + k]);
                        fma2(a1[tt], wy, v[tt + k]);
                    }
                }
            }
            #pragma unroll
            for (int tt = 0; tt < 7; tt++) {
                float2 f0 = unpack2(a0[tt]);
                float2 f1 = unpack2(a1[tt]);
                f0.x = fmaxf(f0.x, 0.f); f0.y = fmaxf(f0.y, 0.f);
                f1.x = fmaxf(f1.x, 0.f); f1.y = fmaxf(f1.y, 0.f);
                *(float2*)&g_h1[((size_t)co0 * 21 + t0 + tt) * 4096 + b0 + bgp * 2] = f0;
                *(float2*)&g_h1[((size_t)co1 * 21 + t0 + tt) * 4096 + b0 + bgp * 2] = f1;
            }
        }
    }
}

// =====================================================================================
// K2: y = relu(relu(conv2_0(h1)) + bd0 + wd0*x) at 9 pts.  f32x2, j-split.  [R13 form]
// =====================================================================================
#define K2_HMAX (100 * 13 * 16)
#define K2_XMAX (30 * 5 * 16)

template<int JC, int TC, int JL>
__device__ __forceinline__ void k2_body(
    const float* __restrict__ h1s, const float* __restrict__ xs2,
    const float* __restrict__ b2_0, const float* __restrict__ bd_0,
    int co0, int bgp, int b0)
{
    const int co1 = co0 + 1;
    ull a[2][JC];
    {
        ull b0v = bcast2(__ldg(b2_0 + co0));
        ull b1v = bcast2(__ldg(b2_0 + co1));
        #pragma unroll
        for (int j = 0; j < JC; j++) { a[0][j] = b0v; a[1][j] = b1v; }
    }
    for (int ci = 0; ci < 100; ci++) {
        const float* hp = &h1s[(ci * TC) * 16 + bgp * 2];
        ull v[TC];
        #pragma unroll
        for (int t = 0; t < TC; t++) v[t] = *(const ull*)&hp[t * 16];
        #pragma unroll
        for (int k = 0; k < 5; k++) {
            float2 w = *(const float2*)&g_w20T[(ci * 5 + k) * 100 + co0];
            ull wx = bcast2(w.x), wy = bcast2(w.y);
            #pragma unroll
            for (int j = 0; j < JC; j++) {
                fma2(a[0][j], wx, v[2 * j + k]);
                fma2(a[1][j], wy, v[2 * j + k]);
            }
        }
    }
    {
        float bd0v = __ldg(bd_0 + co0), bd1v = __ldg(bd_0 + co1);
        #pragma unroll
        for (int j = 0; j < JC; j++) {
            float2 f0 = unpack2(a[0][j]);
            float2 f1 = unpack2(a[1][j]);
            a[0][j] = pack2(fmaxf(f0.x, 0.f) + bd0v, fmaxf(f0.y, 0.f) + bd0v);
            a[1][j] = pack2(fmaxf(f1.x, 0.f) + bd1v, fmaxf(f1.y, 0.f) + bd1v);
        }
    }
    for (int ci = 0; ci < 30; ci++) {
        float2 w = *(const float2*)&g_wd0T[ci * 100 + co0];
        ull wx = bcast2(w.x), wy = bcast2(w.y);
        const float* xp = &xs2[(ci * JC) * 16 + bgp * 2];
        #pragma unroll
        for (int j = 0; j < JC; j++) {
            ull xv = *(const ull*)&xp[j * 16];
            fma2(a[0][j], wx, xv);
            fma2(a[1][j], wy, xv);
        }
    }
    #pragma unroll
    for (int j = 0; j < JC; j++) {
        float2 f0 = unpack2(a[0][j]);
        float2 f1 = unpack2(a[1][j]);
        f0.x = fmaxf(f0.x, 0.f); f0.y = fmaxf(f0.y, 0.f);
        f1.x = fmaxf(f1.x, 0.f); f1.y = fmaxf(f1.y, 0.f);
        *(float2*)&g_y[((size_t)co0 * 9 + JL + j) * 4096 + b0 + bgp * 2] = f0;
        *(float2*)&g_y[((size_t)co1 * 9 + JL + j) * 4096 + b0 + bgp * 2] = f1;
    }
}

__global__ __launch_bounds__(512, 2) void k2(
    const float* __restrict__ x,
    const float* __restrict__ b2_0, const float* __restrict__ bd_0)
{
    extern __shared__ float sm[];
    float* h1s = sm;
    float* xs2 = sm + K2_HMAX;
    const int tid = threadIdx.x;
    const int bq  = blockIdx.x >> 1;
    const int jr  = blockIdx.x & 1;
    const int b0  = bq * 16;
    const int jlo  = jr ? 4 : 0;
    const int jcnt = jr ? 5 : 4;
    const int tlo  = jr ? 8 : 0;
    const int tcnt = jr ? 13 : 12;

    const int nh = (100 * tcnt * 16) >> 2;
    for (int i = tid; i < nh; i += 512) {
        int row = i >> 2, q = i & 3;
        int ci = row / tcnt, tt = row - ci * tcnt;
        cp16(&h1s[row * 16 + 4 * q],
             &g_h1[((size_t)ci * 21 + tlo + tt) * 4096 + b0 + 4 * q]);
    }
    cp_commit();

    const int nx = 30 * jcnt * 16;
    for (int i = tid; i < nx; i += 512) {
        int bl = i & 15; int r = i >> 4; int jj = r % jcnt; int ci = r / jcnt;
        xs2[(ci * jcnt + jj) * 16 + bl] =
            x[(size_t)(b0 + bl) * 7680 + ci * 256 + 239 + 2 * (jlo + jj)];
    }

    cp_wait0();
    __syncthreads();

    const int cop = tid >> 3;
    const int bgp = tid & 7;
    if (cop < 50) {
        const int co0 = 2 * cop;
        if (jr == 0) k2_body<4, 12, 0>(h1s, xs2, b2_0, bd_0, co0, bgp, b0);
        else         k2_body<5, 13, 4>(h1s, xs2, b2_0, bd_0, co0, bgp, b0);
    }
}

// =====================================================================================
// K3: h11 = relu(conv1_1(y, dil=2)) at 5 pts.  R9 scalar/float4 body.
// 8 batches/CTA, 256 thr, occ 4, grid 512 -> SINGLE WAVE.
// =====================================================================================
#define K3_Y8 (100 * 9 * 8)         // 7200 floats
__global__ __launch_bounds__(256, 4) void k3(const float* __restrict__ b1_1)
{
    extern __shared__ float sm[];
    float* ys = sm;
    const int tid = threadIdx.x;
    const int b0  = blockIdx.x * 8;

    for (int i = tid; i < 1800; i += 256) {      // 7200/4 float4s
        int cij = i >> 1, q = i & 1;
        cp16(&ys[cij * 8 + 4 * q], &g_y[(size_t)cij * 4096 + b0 + 4 * q]);
    }
    cp_commit();
    cp_wait0();
    __syncthreads();

    const int cog = tid >> 1;          // 0..127, active < 100 (co pairs)
    const int bg  = tid & 1;           // batch quad (8 batches = 2 quads)
    if (cog < 100) {
        const int co0 = 2 * cog, co1 = co0 + 1;
        float4 a0[5], a1[5];
        {
            float bi0 = __ldg(b1_1 + co0), bi1 = __ldg(b1_1 + co1);
            #pragma unroll
            for (int i = 0; i < 5; i++) {
                a0[i] = make_float4(bi0, bi0, bi0, bi0);
                a1[i] = make_float4(bi1, bi1, bi1, bi1);
            }
        }
        for (int ci = 0; ci < 100; ci++) {
            const float* yp = &ys[(ci * 9) * 8 + bg * 4];
            #pragma unroll
            for (int k = 0; k < 5; k++) {
                float2 w = *(const float2*)&g_w11T[(ci * 5 + k) * 200 + co0];
                #pragma unroll
                for (int i = 0; i < 5; i++) {
                    float4 av = *(const float4*)&yp[(k + i) * 8];
                    fma4(a0[i], w.x, av);
                    fma4(a1[i], w.y, av);
                }
            }
        }
        #pragma unroll
        for (int i = 0; i < 5; i++) {
            float4 r0, r1;
            r0.x = fmaxf(a0[i].x, 0.f); r0.y = fmaxf(a0[i].y, 0.f);
            r0.z = fmaxf(a0[i].z, 0.f); r0.w = fmaxf(a0[i].w, 0.f);
            r1.x = fmaxf(a1[i].x, 0.f); r1.y = fmaxf(a1[i].y, 0.f);
            r1.z = fmaxf(a1[i].z, 0.f); r1.w = fmaxf(a1[i].w, 0.f);
            *(float4*)&g_h11[((size_t)co0 * 5 + i) * 4096 + b0 + bg * 4] = r0;
            *(float4*)&g_h11[((size_t)co1 * 5 + i) * 4096 + b0 + bg * 4] = r1;
        }
    }
}

// =====================================================================================
// K4: feat = relu(relu(conv2_1(h11)@t=255) + bd1 + wd1*y[t=255]); fused head.
// f32x2 body.  8 batches/CTA, 256 thr, occ 4, grid 512 -> SINGLE WAVE.
// =====================================================================================
#define K4_H8   8000                // h11 tile [cik][8]
#define K4_YR8  800                 // yres [ci*8+b]
#define K4_FT8  1608                // feat [b*201+co2]
#define K4_HH8  832                 // smH  [b*104+c1]
__global__ __launch_bounds__(256, 4) void k4(
    const int* __restrict__ task_labels,
    const float* __restrict__ b2_1, const float* __restrict__ bd_1,
    const float* __restrict__ hb1,
    const float* __restrict__ hw2, const float* __restrict__ hb2,
    float* __restrict__ out)
{
    extern __shared__ float sm[];
    float* h11s = sm;
    float* yres = sm + K4_H8;
    float* feat = sm + K4_H8 + K4_YR8;
    float* smH  = sm + K4_H8 + K4_YR8 + K4_FT8;
    const int tid = threadIdx.x;
    const int b0  = blockIdx.x * 8;

    const int cog = tid >> 1;          // 0..127, active < 100
    const int bg  = tid & 1;           // batch quad (8 batches = 2 quads)
    const bool act = (cog < 100);
    const int co0 = 2 * cog, co1 = 2 * cog + 1;

    for (int i = tid; i < 2000; i += 256) {      // 8000/4 float4s
        int cik = i >> 1, q = i & 1;
        cp16(&h11s[cik * 8 + 4 * q], &g_h11[(size_t)cik * 4096 + b0 + 4 * q]);
    }
    cp_commit();

    for (int i = tid; i < K4_YR8; i += 256) {
        int bl = i & 7, ci = i >> 3;
        yres[ci * 8 + bl] = g_y[((size_t)ci * 9 + 8) * 4096 + b0 + bl];
    }

    cp_wait0();
    __syncthreads();

    if (act) {
        ull c0l = 0, c0h = 0, c1l = 0, c1h = 0;
        #pragma unroll 2
        for (int q = 0; q < 250; q++) {
            ulonglong2 av0 = *(const ulonglong2*)&h11s[(4 * q + 0) * 8 + bg * 4];
            ulonglong2 av1 = *(const ulonglong2*)&h11s[(4 * q + 1) * 8 + bg * 4];
            ulonglong2 av2 = *(const ulonglong2*)&h11s[(4 * q + 2) * 8 + bg * 4];
            ulonglong2 av3 = *(const ulonglong2*)&h11s[(4 * q + 3) * 8 + bg * 4];
            float2 w0 = *(const float2*)&g_w2T[(4 * q + 0) * 200 + co0];
            float2 w1 = *(const float2*)&g_w2T[(4 * q + 1) * 200 + co0];
            float2 w2 = *(const float2*)&g_w2T[(4 * q + 2) * 200 + co0];
            float2 w3 = *(const float2*)&g_w2T[(4 * q + 3) * 200 + co0];
            ull w0x = bcast2(w0.x), w0y = bcast2(w0.y);
            ull w1x = bcast2(w1.x), w1y = bcast2(w1.y);
            ull w2x = bcast2(w2.x), w2y = bcast2(w2.y);
            ull w3x = bcast2(w3.x), w3y = bcast2(w3.y);
            fma2(c0l, w0x, av0.x); fma2(c0h, w0x, av0.y);
            fma2(c1l, w0y, av0.x); fma2(c1h, w0y, av0.y);
            fma2(c0l, w1x, av1.x); fma2(c0h, w1x, av1.y);
            fma2(c1l, w1y, av1.x); fma2(c1h, w1y, av1.y);
            fma2(c0l, w2x, av2.x); fma2(c0h, w2x, av2.y);
            fma2(c1l, w2y, av2.x); fma2(c1h, w2y, av2.y);
            fma2(c0l, w3x, av3.x); fma2(c0h, w3x, av3.y);
            fma2(c1l, w3y, av3.x); fma2(c1h, w3y, av3.y);
        }

        ull r0l = 0, r0h = 0, r1l = 0, r1h = 0;
        #pragma unroll 5
        for (int q = 0; q < 25; q++) {
            ulonglong2 yv0 = *(const ulonglong2*)&yres[(4 * q + 0) * 8 + bg * 4];
            ulonglong2 yv1 = *(const ulonglong2*)&yres[(4 * q + 1) * 8 + bg * 4];
            ulonglong2 yv2 = *(const ulonglong2*)&yres[(4 * q + 2) * 8 + bg * 4];
            ulonglong2 yv3 = *(const ulonglong2*)&yres[(4 * q + 3) * 8 + bg * 4];
            float2 w0 = *(const float2*)&g_wdT[(4 * q + 0) * 200 + co0];
            float2 w1 = *(const float2*)&g_wdT[(4 * q + 1) * 200 + co0];
            float2 w2 = *(const float2*)&g_wdT[(4 * q + 2) * 200 + co0];
            float2 w3 = *(const float2*)&g_wdT[(4 * q + 3) * 200 + co0];
            ull w0x = bcast2(w0.x), w0y = bcast2(w0.y);
            ull w1x = bcast2(w1.x), w1y = bcast2(w1.y);
            ull w2x = bcast2(w2.x), w2y = bcast2(w2.y);
            ull w3x = bcast2(w3.x), w3y = bcast2(w3.y);
            fma2(r0l, w0x, yv0.x); fma2(r0h, w0x, yv0.y);
            fma2(r1l, w0y, yv0.x); fma2(r1h, w0y, yv0.y);
            fma2(r0l, w1x, yv1.x); fma2(r0h, w1x, yv1.y);
            fma2(r1l, w1y, yv1.x); fma2(r1h, w1y, yv1.y);
            fma2(r0l, w2x, yv2.x); fma2(r0h, w2x, yv2.y);
            fma2(r1l, w2y, yv2.x); fma2(r1h, w2y, yv2.y);
            fma2(r0l, w3x, yv3.x); fma2(r0h, w3x, yv3.y);
            fma2(r1l, w3y, yv3.x); fma2(r1h, w3y, yv3.y);
        }

        float b2v0 = __ldg(b2_1 + co0), bdv0 = __ldg(bd_1 + co0);
        float b2v1 = __ldg(b2_1 + co1), bdv1 = __ldg(bd_1 + co1);
        float2 cl0 = unpack2(c0l), ch0 = unpack2(c0h);
        float2 cl1 = unpack2(c1l), ch1 = unpack2(c1h);
        float2 sl0 = unpack2(r0l), sh0 = unpack2(r0h);
        float2 sl1 = unpack2(r1l), sh1 = unpack2(r1h);
        float conv0[4] = { cl0.x, cl0.y, ch0.x, ch0.y };
        float conv1[4] = { cl1.x, cl1.y, ch1.x, ch1.y };
        float res0[4]  = { sl0.x, sl0.y, sh0.x, sh0.y };
        float res1[4]  = { sl1.x, sl1.y, sh1.x, sh1.y };
        #pragma unroll
        for (int b = 0; b < 4; b++) {
            int blx = bg * 4 + b;
            feat[blx * 201 + co0] = fmaxf(fmaxf(conv0[b] + b2v0, 0.f) + bdv0 + res0[b], 0.f);
            feat[blx * 201 + co1] = fmaxf(fmaxf(conv1[b] + b2v1, 0.f) + bdv1 + res1[b], 0.f);
        }
    }
    __syncthreads();

    // head A: 8 batches x 50 c1-pairs = 400 outputs
    for (int o = tid; o < 400; o += 256) {
        int blx = o / 50, c1p = o - blx * 50;
        int task = __ldg(task_labels + b0 + blx);
        const float* Wt = g_hw1T + task * 20000 + c1p * 2;
        const float* fr = &feat[blx * 201];
        ull acc = 0;
        #pragma unroll 4
        for (int c2 = 0; c2 < 200; c2++) {
            float2 w = *(const float2*)&Wt[c2 * 100];
            ull wp; asm("mov.b64 %0, {%1, %2};" : "=l"(wp) : "f"(w.x), "f"(w.y));
            fma2(acc, bcast2(fr[c2]), wp);
        }
        float2 s = unpack2(acc);
        float2 hb = *(const float2*)&hb1[task * 100 + c1p * 2];
        smH[blx * 104 + c1p * 2 + 0] = tanhf(s.x + hb.x);
        smH[blx * 104 + c1p * 2 + 1] = tanhf(s.y + hb.y);
    }
    __syncthreads();

    // head B
    if (tid < 8) {
        int blx = tid;
        int task = __ldg(task_labels + b0 + blx);
        const float4* W = (const float4*)(hw2 + task * 100);
        const float* hr = &smH[blx * 104];
        float a0 = 0.f, a1 = 0.f, a2 = 0.f, a3 = 0.f;
        #pragma unroll 5
        for (int q = 0; q < 25; q++) {
            float4 wv = __ldg(W + q);
            a0 = fmaf(hr[4 * q + 0], wv.x, a0);
            a1 = fmaf(hr[4 * q + 1], wv.y, a1);
            a2 = fmaf(hr[4 * q + 2], wv.z, a2);
            a3 = fmaf(hr[4 * q + 3], wv.w, a3);
        }
        out[b0 + blx] = (a0 + a1) + (a2 + a3) + __ldg(hb2 + task);
    }
}

// =====================================================================================
extern "C" void kernel_launch(void* const* d_in, const int* in_sizes, int n_in,
                              void* d_out, int out_size)
{
    const float* x    = (const float*)d_in[0];
    const int*   tl   = (const int*)  d_in[1];
    const float* w1_0 = (const float*)d_in[2];
    const float* b1_0 = (const float*)d_in[3];
    const float* w2_0 = (const float*)d_in[4];
    const float* b2_0 = (const float*)d_in[5];
    const float* wd_0 = (const float*)d_in[6];
    const float* bd_0 = (const float*)d_in[7];
    const float* w1_1 = (const float*)d_in[8];
    const float* b1_1 = (const float*)d_in[9];
    const float* w2_1 = (const float*)d_in[10];
    const float* b2_1 = (const float*)d_in[11];
    const float* wd_1 = (const float*)d_in[12];
    const float* bd_1 = (const float*)d_in[13];
    const float* hw1  = (const float*)d_in[14];
    const float* hb1  = (const float*)d_in[15];
    const float* hw2  = (const float*)d_in[16];
    const float* hb2  = (const float*)d_in[17];
    float* out = (float*)d_out;

    const int s1 = K1_X * 4;                              // 24,000 B
    const int s2 = (K2_HMAX + K2_XMAX) * 4;               // 92,800 B
    const int s3 = K3_Y8 * 4;                             // 28,800 B
    const int s4 = (K4_H8 + K4_YR8 + K4_FT8 + K4_HH8) * 4;// 44,960 B
    cudaFuncSetAttribute(k1, cudaFuncAttributeMaxDynamicSharedMemorySize, s1);
    cudaFuncSetAttribute(k2, cudaFuncAttributeMaxDynamicSharedMemorySize, s2);
    cudaFuncSetAttribute(k3, cudaFuncAttributeMaxDynamicSharedMemorySize, s3);
    cudaFuncSetAttribute(k4, cudaFuncAttributeMaxDynamicSharedMemorySize, s4);

    k0<<<148, 512>>>(w2_1, wd_1, hw1, w2_0, w1_1, wd_0, w1_0);
    k1<<<512, 256, s1>>>(x, b1_0);
    k2<<<512, 512, s2>>>(x, b2_0, bd_0);
    k3<<<512, 256, s3>>>(b1_1);
    k4<<<512, 256, s4>>>(tl, b2_1, bd_1, hb1, hw2, hb2, out);
}

// round 17
// speedup vs baseline: 1.0539x; 1.0264x over previous
#include <cuda_runtime.h>
#include <cstddef>
#include <cstdint>

typedef unsigned long long ull;

// ---------------- gmem scratch ----------------
__device__ float g_h1 [100 * 21 * 4096];
__device__ float g_y  [100 *  9 * 4096];
__device__ float g_h11[200 *  5 * 4096];
// transposed weights (filled by k0 each launch)
__device__ float g_w2T [1000 * 200];    // w2_1: [cik][co]
__device__ float g_wdT [100 * 200];     // wd_1: [ci][co]
__device__ float g_hw1T[8 * 200 * 100]; // hw1:  [task][c2][c1]
__device__ float g_w20T[500 * 100];     // w2_0: [cik][co]
__device__ float g_w11T[500 * 200];     // w1_1: [cik][co]
__device__ float g_wd0T[30 * 100];      // wd_0: [ci][co]
__device__ float g_w10T[150 * 100];     // w1_0: [cik][co]

// ---------------- helpers ----------------
__device__ __forceinline__ void cp16(float* dst_smem, const float* src) {
    uint32_t s = (uint32_t)__cvta_generic_to_shared(dst_smem);
    asm volatile("cp.async.cg.shared.global [%0], [%1], 16;\n" :: "r"(s), "l"(src));
}
__device__ __forceinline__ void cp_commit() { asm volatile("cp.async.commit_group;\n"); }
__device__ __forceinline__ void cp_wait0()  { asm volatile("cp.async.wait_group 0;\n"); }

__device__ __forceinline__ ull pack2(float x, float y) {
    ull r; asm("mov.b64 %0, {%1, %2};" : "=l"(r) : "f"(x), "f"(y)); return r;
}
__device__ __forceinline__ ull bcast2(float x) { return pack2(x, x); }
__device__ __forceinline__ float2 unpack2(ull v) {
    float2 f; asm("mov.b64 {%0, %1}, %2;" : "=f"(f.x), "=f"(f.y) : "l"(v)); return f;
}
__device__ __forceinline__ void fma2(ull& d, ull a, ull b) {
    asm("fma.rn.f32x2 %0, %1, %2, %3;" : "=l"(d) : "l"(a), "l"(b), "l"(d));
}

// =====================================================================================
// K0: weight transposes — coalesced reads, scattered writes
// =====================================================================================
__global__ __launch_bounds__(512, 2) void k0(
    const float* __restrict__ w2_1, const float* __restrict__ wd_1,
    const float* __restrict__ hw1,  const float* __restrict__ w2_0,
    const float* __restrict__ w1_1, const float* __restrict__ wd_0,
    const float* __restrict__ w1_0)
{
    const int i = blockIdx.x * blockDim.x + threadIdx.x;
    const int n = blockDim.x * gridDim.x;
    for (int j = i; j < 200000; j += n) {          // w2_1 [co][cik] -> [cik][co]
        int co = j / 1000, cik = j - co * 1000;
        g_w2T[cik * 200 + co] = __ldg(w2_1 + j);
    }
    for (int j = i; j < 20000; j += n) {           // wd_1 [co][ci] -> [ci][co]
        int co = j / 100, ci = j - co * 100;
        g_wdT[ci * 200 + co] = __ldg(wd_1 + j);
    }
    for (int j = i; j < 160000; j += n) {          // hw1 [t][c1][c2] -> [t][c2][c1]
        int t = j / 20000; int r = j - t * 20000; int c1 = r / 200; int c2 = r - c1 * 200;
        g_hw1T[t * 20000 + c2 * 100 + c1] = __ldg(hw1 + j);
    }
    for (int j = i; j < 50000; j += n) {           // w2_0 [co][cik] -> [cik][co]
        int co = j / 500, cik = j - co * 500;
        g_w20T[cik * 100 + co] = __ldg(w2_0 + j);
    }
    for (int j = i; j < 100000; j += n) {          // w1_1 [co][cik] -> [cik][co]
        int co = j / 500, cik = j - co * 500;
        g_w11T[cik * 200 + co] = __ldg(w1_1 + j);
    }
    for (int j = i; j < 3000; j += n) {            // wd_0 [co][ci] -> [ci][co]
        int co = j / 30, ci = j - co * 30;
        g_wd0T[ci * 100 + co] = __ldg(wd_0 + j);
    }
    for (int j = i; j < 15000; j += n) {           // w1_0 [co][cik] -> [cik][co]
        int co = j / 150, cik = j - co * 150;
        g_w10T[cik * 100 + co] = __ldg(w1_0 + j);
    }
}

// =====================================================================================
// K1: h1 = relu(conv1_0(x)).  f32x2, 3 t-phases.  8 batches/CTA, 256 thr, occ 4.
// =====================================================================================
#define K1_X 6000                   // [(ci*25+tau)*8 + bl]
__global__ __launch_bounds__(256, 4) void k1(
    const float* __restrict__ x, const float* __restrict__ b1_0)
{
    extern __shared__ float sm[];
    const int tid = threadIdx.x;
    const int b0  = blockIdx.x * 8;

    for (int i = tid; i < K1_X; i += 256) {
        int ci = i / 200; int r = i - ci * 200; int bl = r / 25; int tau = r - bl * 25;
        sm[(ci * 25 + tau) * 8 + bl] = x[(size_t)(b0 + bl) * 7680 + ci * 256 + 231 + tau];
    }
    __syncthreads();

    const int cop = tid >> 2;          // 0..63, active < 50
    const int bgp = tid & 3;           // batch pair (8 batches = 4 pairs)
    if (cop < 50) {
        const int co0 = 2 * cop, co1 = co0 + 1;
        const float bi0 = __ldg(b1_0 + co0), bi1 = __ldg(b1_0 + co1);
        #pragma unroll 1
        for (int ph = 0; ph < 3; ph++) {
            const int t0 = ph * 7;
            ull a0[7], a1[7];
            {
                ull p0 = bcast2(bi0), p1 = bcast2(bi1);
                #pragma unroll
                for (int tt = 0; tt < 7; tt++) { a0[tt] = p0; a1[tt] = p1; }
            }
            for (int ci = 0; ci < 30; ci++) {
                const float* xp = &sm[(ci * 25 + t0) * 8 + bgp * 2];
                ull v[11];
                #pragma unroll
                for (int u = 0; u < 11; u++) v[u] = *(const ull*)&xp[u * 8];
                #pragma unroll
                for (int k = 0; k < 5; k++) {
                    float2 w = *(const float2*)&g_w10T[(ci * 5 + k) * 100 + co0];
                    ull wx = bcast2(w.x), wy = bcast2(w.y);
                    #pragma unroll
                    for (int tt = 0; tt < 7; tt++) {
                        fma2(a0[tt], wx, v[tt + k]);
                        fma2(a1[tt], wy, v[tt + k]);
                    }
                }
            }
            #pragma unroll
            for (int tt = 0; tt < 7; tt++) {
                float2 f0 = unpack2(a0[tt]);
                float2 f1 = unpack2(a1[tt]);
                f0.x = fmaxf(f0.x, 0.f); f0.y = fmaxf(f0.y, 0.f);
                f1.x = fmaxf(f1.x, 0.f); f1.y = fmaxf(f1.y, 0.f);
                *(float2*)&g_h1[((size_t)co0 * 21 + t0 + tt) * 4096 + b0 + bgp * 2] = f0;
                *(float2*)&g_h1[((size_t)co1 * 21 + t0 + tt) * 4096 + b0 + bgp * 2] = f1;
            }
        }
    }
}

// =====================================================================================
// K2: y = relu(relu(conv2_0(h1)) + bd0 + wd0*x) at 9 pts.  f32x2, j-split.  [R13 form]
// =====================================================================================
#define K2_HMAX (100 * 13 * 16)
#define K2_XMAX (30 * 5 * 16)

template<int JC, int TC, int JL>
__device__ __forceinline__ void k2_body(
    const float* __restrict__ h1s, const float* __restrict__ xs2,
    const float* __restrict__ b2_0, const float* __restrict__ bd_0,
    int co0, int bgp, int b0)
{
    const int co1 = co0 + 1;
    ull a[2][JC];
    {
        ull b0v = bcast2(__ldg(b2_0 + co0));
        ull b1v = bcast2(__ldg(b2_0 + co1));
        #pragma unroll
        for (int j = 0; j < JC; j++) { a[0][j] = b0v; a[1][j] = b1v; }
    }
    for (int ci = 0; ci < 100; ci++) {
        const float* hp = &h1s[(ci * TC) * 16 + bgp * 2];
        ull v[TC];
        #pragma unroll
        for (int t = 0; t < TC; t++) v[t] = *(const ull*)&hp[t * 16];
        #pragma unroll
        for (int k = 0; k < 5; k++) {
            float2 w = *(const float2*)&g_w20T[(ci * 5 + k) * 100 + co0];
            ull wx = bcast2(w.x), wy = bcast2(w.y);
            #pragma unroll
            for (int j = 0; j < JC; j++) {
                fma2(a[0][j], wx, v[2 * j + k]);
                fma2(a[1][j], wy, v[2 * j + k]);
            }
        }
    }
    {
        float bd0v = __ldg(bd_0 + co0), bd1v = __ldg(bd_0 + co1);
        #pragma unroll
        for (int j = 0; j < JC; j++) {
            float2 f0 = unpack2(a[0][j]);
            float2 f1 = unpack2(a[1][j]);
            a[0][j] = pack2(fmaxf(f0.x, 0.f) + bd0v, fmaxf(f0.y, 0.f) + bd0v);
            a[1][j] = pack2(fmaxf(f1.x, 0.f) + bd1v, fmaxf(f1.y, 0.f) + bd1v);
        }
    }
    for (int ci = 0; ci < 30; ci++) {
        float2 w = *(const float2*)&g_wd0T[ci * 100 + co0];
        ull wx = bcast2(w.x), wy = bcast2(w.y);
        const float* xp = &xs2[(ci * JC) * 16 + bgp * 2];
        #pragma unroll
        for (int j = 0; j < JC; j++) {
            ull xv = *(const ull*)&xp[j * 16];
            fma2(a[0][j], wx, xv);
            fma2(a[1][j], wy, xv);
        }
    }
    #pragma unroll
    for (int j = 0; j < JC; j++) {
        float2 f0 = unpack2(a[0][j]);
        float2 f1 = unpack2(a[1][j]);
        f0.x = fmaxf(f0.x, 0.f); f0.y = fmaxf(f0.y, 0.f);
        f1.x = fmaxf(f1.x, 0.f); f1.y = fmaxf(f1.y, 0.f);
        *(float2*)&g_y[((size_t)co0 * 9 + JL + j) * 4096 + b0 + bgp * 2] = f0;
        *(float2*)&g_y[((size_t)co1 * 9 + JL + j) * 4096 + b0 + bgp * 2] = f1;
    }
}

__global__ __launch_bounds__(512, 2) void k2(
    const float* __restrict__ x,
    const float* __restrict__ b2_0, const float* __restrict__ bd_0)
{
    extern __shared__ float sm[];
    float* h1s = sm;
    float* xs2 = sm + K2_HMAX;
    const int tid = threadIdx.x;
    const int bq  = blockIdx.x >> 1;
    const int jr  = blockIdx.x & 1;
    const int b0  = bq * 16;
    const int jlo  = jr ? 4 : 0;
    const int jcnt = jr ? 5 : 4;
    const int tlo  = jr ? 8 : 0;
    const int tcnt = jr ? 13 : 12;

    const int nh = (100 * tcnt * 16) >> 2;
    for (int i = tid; i < nh; i += 512) {
        int row = i >> 2, q = i & 3;
        int ci = row / tcnt, tt = row - ci * tcnt;
        cp16(&h1s[row * 16 + 4 * q],
             &g_h1[((size_t)ci * 21 + tlo + tt) * 4096 + b0 + 4 * q]);
    }
    cp_commit();

    const int nx = 30 * jcnt * 16;
    for (int i = tid; i < nx; i += 512) {
        int bl = i & 15; int r = i >> 4; int jj = r % jcnt; int ci = r / jcnt;
        xs2[(ci * jcnt + jj) * 16 + bl] =
            x[(size_t)(b0 + bl) * 7680 + ci * 256 + 239 + 2 * (jlo + jj)];
    }

    cp_wait0();
    __syncthreads();

    const int cop = tid >> 3;
    const int bgp = tid & 7;
    if (cop < 50) {
        const int co0 = 2 * cop;
        if (jr == 0) k2_body<4, 12, 0>(h1s, xs2, b2_0, bd_0, co0, bgp, b0);
        else         k2_body<5, 13, 4>(h1s, xs2, b2_0, bd_0, co0, bgp, b0);
    }
}

// =====================================================================================
// K3: h11 = relu(conv1_1(y, dil=2)) at 5 pts.  f32x2, k1-style.
// 200 channels = 100 co-pairs covered in TWO m-iterations (cop = tid>>2 + 64m).
// Per-iteration regs: a0[5]+a1[5] (20) + v[9] (18) ~= 55.  occ 4, single wave.
// =====================================================================================
#define K3_Y8 (100 * 9 * 8)         // 7200 floats
__global__ __launch_bounds__(256, 4) void k3(const float* __restrict__ b1_1)
{
    extern __shared__ float sm[];
    float* ys = sm;
    const int tid = threadIdx.x;
    const int b0  = blockIdx.x * 8;

    for (int i = tid; i < 1800; i += 256) {      // 7200/4 float4s
        int cij = i >> 1, q = i & 1;
        cp16(&ys[cij * 8 + 4 * q], &g_y[(size_t)cij * 4096 + b0 + 4 * q]);
    }
    cp_commit();
    cp_wait0();
    __syncthreads();

    const int bgp = tid & 3;           // batch pair (8 batches = 4 pairs)
    #pragma unroll 1
    for (int m = 0; m < 2; m++) {
        const int cop = (tid >> 2) + 64 * m;     // 0..63, then 64..127; active < 100
        if (cop < 100) {
            const int co0 = 2 * cop, co1 = co0 + 1;
            ull a0[5], a1[5];
            {
                ull p0 = bcast2(__ldg(b1_1 + co0));
                ull p1 = bcast2(__ldg(b1_1 + co1));
                #pragma unroll
                for (int i = 0; i < 5; i++) { a0[i] = p0; a1[i] = p1; }
            }
            for (int ci = 0; ci < 100; ci++) {
                const float* yp = &ys[(ci * 9) * 8 + bgp * 2];
                ull v[9];
                #pragma unroll
                for (int j = 0; j < 9; j++) v[j] = *(const ull*)&yp[j * 8];
                #pragma unroll
                for (int k = 0; k < 5; k++) {
                    float2 w = *(const float2*)&g_w11T[(ci * 5 + k) * 200 + co0];
                    ull wx = bcast2(w.x), wy = bcast2(w.y);
                    #pragma unroll
                    for (int i = 0; i < 5; i++) {
                        fma2(a0[i], wx, v[k + i]);
                        fma2(a1[i], wy, v[k + i]);
                    }
                }
            }
            #pragma unroll
            for (int i = 0; i < 5; i++) {
                float2 f0 = unpack2(a0[i]);
                float2 f1 = unpack2(a1[i]);
                f0.x = fmaxf(f0.x, 0.f); f0.y = fmaxf(f0.y, 0.f);
                f1.x = fmaxf(f1.x, 0.f); f1.y = fmaxf(f1.y, 0.f);
                *(float2*)&g_h11[((size_t)co0 * 5 + i) * 4096 + b0 + bgp * 2] = f0;
                *(float2*)&g_h11[((size_t)co1 * 5 + i) * 4096 + b0 + bgp * 2] = f1;
            }
        }
    }
}

// =====================================================================================
// K4: feat = relu(relu(conv2_1(h11)@t=255) + bd1 + wd1*y[t=255]); fused head.
// f32x2 body.  8 batches/CTA, 256 thr, occ 4, single wave.  [R15 form]
// =====================================================================================
#define K4_H8   8000                // h11 tile [cik][8]
#define K4_YR8  800                 // yres [ci*8+b]
#define K4_FT8  1608                // feat [b*201+co2]
#define K4_HH8  832                 // smH  [b*104+c1]
__global__ __launch_bounds__(256, 4) void k4(
    const int* __restrict__ task_labels,
    const float* __restrict__ b2_1, const float* __restrict__ bd_1,
    const float* __restrict__ hb1,
    const float* __restrict__ hw2, const float* __restrict__ hb2,
    float* __restrict__ out)
{
    extern __shared__ float sm[];
    float* h11s = sm;
    float* yres = sm + K4_H8;
    float* feat = sm + K4_H8 + K4_YR8;
    float* smH  = sm + K4_H8 + K4_YR8 + K4_FT8;
    const int tid = threadIdx.x;
    const int b0  = blockIdx.x * 8;

    const int cog = tid >> 1;          // 0..127, active < 100
    const int bg  = tid & 1;           // batch quad (8 batches = 2 quads)
    const bool act = (cog < 100);
    const int co0 = 2 * cog, co1 = 2 * cog + 1;

    for (int i = tid; i < 2000; i += 256) {      // 8000/4 float4s
        int cik = i >> 1, q = i & 1;
        cp16(&h11s[cik * 8 + 4 * q], &g_h11[(size_t)cik * 4096 + b0 + 4 * q]);
    }
    cp_commit();

    for (int i = tid; i < K4_YR8; i += 256) {
        int bl = i & 7, ci = i >> 3;
        yres[ci * 8 + bl] = g_y[((size_t)ci * 9 + 8) * 4096 + b0 + bl];
    }

    cp_wait0();
    __syncthreads();

    if (act) {
        ull c0l = 0, c0h = 0, c1l = 0, c1h = 0;
        #pragma unroll 2
        for (int q = 0; q < 250; q++) {
            ulonglong2 av0 = *(const ulonglong2*)&h11s[(4 * q + 0) * 8 + bg * 4];
            ulonglong2 av1 = *(const ulonglong2*)&h11s[(4 * q + 1) * 8 + bg * 4];
            ulonglong2 av2 = *(const ulonglong2*)&h11s[(4 * q + 2) * 8 + bg * 4];
            ulonglong2 av3 = *(const ulonglong2*)&h11s[(4 * q + 3) * 8 + bg * 4];
            float2 w0 = *(const float2*)&g_w2T[(4 * q + 0) * 200 + co0];
            float2 w1 = *(const float2*)&g_w2T[(4 * q + 1) * 200 + co0];
            float2 w2 = *(const float2*)&g_w2T[(4 * q + 2) * 200 + co0];
            float2 w3 = *(const float2*)&g_w2T[(4 * q + 3) * 200 + co0];
            ull w0x = bcast2(w0.x), w0y = bcast2(w0.y);
            ull w1x = bcast2(w1.x), w1y = bcast2(w1.y);
            ull w2x = bcast2(w2.x), w2y = bcast2(w2.y);
            ull w3x = bcast2(w3.x), w3y = bcast2(w3.y);
            fma2(c0l, w0x, av0.x); fma2(c0h, w0x, av0.y);
            fma2(c1l, w0y, av0.x); fma2(c1h, w0y, av0.y);
            fma2(c0l, w1x, av1.x); fma2(c0h, w1x, av1.y);
            fma2(c1l, w1y, av1.x); fma2(c1h, w1y, av1.y);
            fma2(c0l, w2x, av2.x); fma2(c0h, w2x, av2.y);
            fma2(c1l, w2y, av2.x); fma2(c1h, w2y, av2.y);
            fma2(c0l, w3x, av3.x); fma2(c0h, w3x, av3.y);
            fma2(c1l, w3y, av3.x); fma2(c1h, w3y, av3.y);
        }

        ull r0l = 0, r0h = 0, r1l = 0, r1h = 0;
        #pragma unroll 5
        for (int q = 0; q < 25; q++) {
            ulonglong2 yv0 = *(const ulonglong2*)&yres[(4 * q + 0) * 8 + bg * 4];
            ulonglong2 yv1 = *(const ulonglong2*)&yres[(4 * q + 1) * 8 + bg * 4];
            ulonglong2 yv2 = *(const ulonglong2*)&yres[(4 * q + 2) * 8 + bg * 4];
            ulonglong2 yv3 = *(const ulonglong2*)&yres[(4 * q + 3) * 8 + bg * 4];
            float2 w0 = *(const float2*)&g_wdT[(4 * q + 0) * 200 + co0];
            float2 w1 = *(const float2*)&g_wdT[(4 * q + 1) * 200 + co0];
            float2 w2 = *(const float2*)&g_wdT[(4 * q + 2) * 200 + co0];
            float2 w3 = *(const float2*)&g_wdT[(4 * q + 3) * 200 + co0];
            ull w0x = bcast2(w0.x), w0y = bcast2(w0.y);
            ull w1x = bcast2(w1.x), w1y = bcast2(w1.y);
            ull w2x = bcast2(w2.x), w2y = bcast2(w2.y);
            ull w3x = bcast2(w3.x), w3y = bcast2(w3.y);
            fma2(r0l, w0x, yv0.x); fma2(r0h, w0x, yv0.y);
            fma2(r1l, w0y, yv0.x); fma2(r1h, w0y, yv0.y);
            fma2(r0l, w1x, yv1.x); fma2(r0h, w1x, yv1.y);
            fma2(r1l, w1y, yv1.x); fma2(r1h, w1y, yv1.y);
            fma2(r0l, w2x, yv2.x); fma2(r0h, w2x, yv2.y);
            fma2(r1l, w2y, yv2.x); fma2(r1h, w2y, yv2.y);
            fma2(r0l, w3x, yv3.x); fma2(r0h, w3x, yv3.y);
            fma2(r1l, w3y, yv3.x); fma2(r1h, w3y, yv3.y);
        }

        float b2v0 = __ldg(b2_1 + co0), bdv0 = __ldg(bd_1 + co0);
        float b2v1 = __ldg(b2_1 + co1), bdv1 = __ldg(bd_1 + co1);
        float2 cl0 = unpack2(c0l), ch0 = unpack2(c0h);
        float2 cl1 = unpack2(c1l), ch1 = unpack2(c1h);
        float2 sl0 = unpack2(r0l), sh0 = unpack2(r0h);
        float2 sl1 = unpack2(r1l), sh1 = unpack2(r1h);
        float conv0[4] = { cl0.x, cl0.y, ch0.x, ch0.y };
        float conv1[4] = { cl1.x, cl1.y, ch1.x, ch1.y };
        float res0[4]  = { sl0.x, sl0.y, sh0.x, sh0.y };
        float res1[4]  = { sl1.x, sl1.y, sh1.x, sh1.y };
        #pragma unroll
        for (int b = 0; b < 4; b++) {
            int blx = bg * 4 + b;
            feat[blx * 201 + co0] = fmaxf(fmaxf(conv0[b] + b2v0, 0.f) + bdv0 + res0[b], 0.f);
            feat[blx * 201 + co1] = fmaxf(fmaxf(conv1[b] + b2v1, 0.f) + bdv1 + res1[b], 0.f);
        }
    }
    __syncthreads();

    // head A: 8 batches x 50 c1-pairs = 400 outputs
    for (int o = tid; o < 400; o += 256) {
        int blx = o / 50, c1p = o - blx * 50;
        int task = __ldg(task_labels + b0 + blx);
        const float* Wt = g_hw1T + task * 20000 + c1p * 2;
        const float* fr = &feat[blx * 201];
        ull acc = 0;
        #pragma unroll 4
        for (int c2 = 0; c2 < 200; c2++) {
            float2 w = *(const float2*)&Wt[c2 * 100];
            ull wp; asm("mov.b64 %0, {%1, %2};" : "=l"(wp) : "f"(w.x), "f"(w.y));
            fma2(acc, bcast2(fr[c2]), wp);
        }
        float2 s = unpack2(acc);
        float2 hb = *(const float2*)&hb1[task * 100 + c1p * 2];
        smH[blx * 104 + c1p * 2 + 0] = tanhf(s.x + hb.x);
        smH[blx * 104 + c1p * 2 + 1] = tanhf(s.y + hb.y);
    }
    __syncthreads();

    // head B
    if (tid < 8) {
        int blx = tid;
        int task = __ldg(task_labels + b0 + blx);
        const float4* W = (const float4*)(hw2 + task * 100);
        const float* hr = &smH[blx * 104];
        float a0 = 0.f, a1 = 0.f, a2 = 0.f, a3 = 0.f;
        #pragma unroll 5
        for (int q = 0; q < 25; q++) {
            float4 wv = __ldg(W + q);
            a0 = fmaf(hr[4 * q + 0], wv.x, a0);
            a1 = fmaf(hr[4 * q + 1], wv.y, a1);
            a2 = fmaf(hr[4 * q + 2], wv.z, a2);
            a3 = fmaf(hr[4 * q + 3], wv.w, a3);
        }
        out[b0 + blx] = (a0 + a1) + (a2 + a3) + __ldg(hb2 + task);
    }
}

// =====================================================================================
extern "C" void kernel_launch(void* const* d_in, const int* in_sizes, int n_in,
                              void* d_out, int out_size)
{
    const float* x    = (const float*)d_in[0];
    const int*   tl   = (const int*)  d_in[1];
    const float* w1_0 = (const float*)d_in[2];
    const float* b1_0 = (const float*)d_in[3];
    const float* w2_0 = (const float*)d_in[4];
    const float* b2_0 = (const float*)d_in[5];
    const float* wd_0 = (const float*)d_in[6];
    const float* bd_0 = (const float*)d_in[7];
    const float* w1_1 = (const float*)d_in[8];
    const float* b1_1 = (const float*)d_in[9];
    const float* w2_1 = (const float*)d_in[10];
    const float* b2_1 = (const float*)d_in[11];
    const float* wd_1 = (const float*)d_in[12];
    const float* bd_1 = (const float*)d_in[13];
    const float* hw1  = (const float*)d_in[14];
    const float* hb1  = (const float*)d_in[15];
    const float* hw2  = (const float*)d_in[16];
    const float* hb2  = (const float*)d_in[17];
    float* out = (float*)d_out;

    const int s1 = K1_X * 4;                              // 24,000 B
    const int s2 = (K2_HMAX + K2_XMAX) * 4;               // 92,800 B
    const int s3 = K3_Y8 * 4;                             // 28,800 B
    const int s4 = (K4_H8 + K4_YR8 + K4_FT8 + K4_HH8) * 4;// 44,960 B
    cudaFuncSetAttribute(k1, cudaFuncAttributeMaxDynamicSharedMemorySize, s1);
    cudaFuncSetAttribute(k2, cudaFuncAttributeMaxDynamicSharedMemorySize, s2);
    cudaFuncSetAttribute(k3, cudaFuncAttributeMaxDynamicSharedMemorySize, s3);
    cudaFuncSetAttribute(k4, cudaFuncAttributeMaxDynamicSharedMemorySize, s4);

    k0<<<148, 512>>>(w2_1, wd_1, hw1, w2_0, w1_1, wd_0, w1_0);
    k1<<<512, 256, s1>>>(x, b1_0);
    k2<<<512, 512, s2>>>(x, b2_0, bd_0);
    k3<<<512, 256, s3>>>(b1_1);
    k4<<<512, 256, s4>>>(tl, b2_1, bd_1, hb1, hw2, hb2, out);
}